// round 8
// baseline (speedup 1.0000x reference)
#include <cuda_runtime.h>
#include <cuda_bf16.h>
#include <cuda_fp16.h>
#include <mma.h>
#include <cstdint>

using namespace nvcuda;

#define N_NODES 50000
#define N_EDGES 800000
#define IN_CH   256
#define HC      128
#define EPS_F   1.000001f

// ================= scratch (static device arrays; no allocation) =================
__device__ __nv_bfloat16 g_Bt[2][3][HC][IN_CH];     // [hi/lo][mat][n][k]  (B = W^T, bf16 split)
__device__ __half g_xh[2][(size_t)N_NODES * HC];    // fp16 messages: x@Wl, x@Wu
__device__ float  g_xs[(size_t)N_NODES * HC];       // fp32 skip: (x@Ws)*EPS
__device__ float2 g_alpha[4][N_NODES];              // [l_src, l_dst, u_src, u_dst][n] = (h0,h1)
__device__ float  g_w[2][N_EDGES];                  // per-edge head-0 softmax weight
__device__ int    g_rp[2][N_NODES + 1];             // CSR row ptr (tgt sorted)

// ================= 1) B = W^T split into bf16 hi/lo =================
__global__ void prep_bt(const float* __restrict__ Wl, const float* __restrict__ Wu,
                        const float* __restrict__ Ws) {
    int i = blockIdx.x * blockDim.x + threadIdx.x;
    if (i >= 3 * HC * IN_CH) return;
    int mat = i / (HC * IN_CH);
    int r   = i % (HC * IN_CH);
    int n = r / IN_CH, k = r % IN_CH;
    const float* W = (mat == 0) ? Wl : (mat == 1 ? Wu : Ws);
    float w = W[k * HC + n];
    __nv_bfloat16 hi = __float2bfloat16(w);
    __nv_bfloat16 lo = __float2bfloat16(w - __bfloat162float(hi));
    g_Bt[0][mat][n][k] = hi;
    g_Bt[1][mat][n][k] = lo;
}

// ================= 2) row pointers via binary search =================
__global__ void rowptr_kernel(const int* __restrict__ ltgt, const int* __restrict__ utgt) {
    int t = blockIdx.x * blockDim.x + threadIdx.x;
    if (t > N_NODES) return;
    #pragma unroll
    for (int s = 0; s < 2; s++) {
        const int* tg = (s == 0) ? ltgt : utgt;
        int lo = 0, hi = N_EDGES;
        while (lo < hi) {
            int mid = (lo + hi) >> 1;
            if (tg[mid] < t) lo = mid + 1; else hi = mid;
        }
        g_rp[s][t] = lo;
    }
}

// ================= 3) wmma GEMM: B resident, A double-buffered, 1 sync/chunk =================
// grid = (3 matrices, 391 M-tiles), 256 threads (8 warps, 4x2 warp grid, warp tile 32x64)
#define KC      64
#define NCHUNK  (IN_CH / KC)     // 4
#define LDA     72               // 64 + 8 pad (bf16); 9x8 granules -> LDSM conflict-free
#define LDB     264              // 256 + 8 pad (bf16); 33x8 granules -> conflict-free
#define ATILE   (128 * LDA)      // elements per A half-tile
#define SM_AVEC 0                // 256 floats
#define SM_A    1024             // 2 buffers x (hi+lo) = 4 x 18432 B
#define SM_B    (SM_A + 4 * ATILE * 2)          // 74752
#define SM_TOTAL (SM_B + 2 * 128 * LDB * 2)     // 209920 B
#define LDC     132              // fp32 C staging stride

__global__ __launch_bounds__(256) void gemm_wmma(const float* __restrict__ X,
                                                 const float* __restrict__ asl, const float* __restrict__ adl,
                                                 const float* __restrict__ asu, const float* __restrict__ adu) {
    extern __shared__ __align__(16) char smem[];
    float* avec = (float*)(smem + SM_AVEC);
    __nv_bfloat16* Bs = (__nv_bfloat16*)(smem + SM_B);   // hi at 0, lo at +128*LDB

    const int tid = threadIdx.x;
    const int wid = tid >> 5;
    const int bx  = blockIdx.x;                 // matrix 0=lower,1=upper,2=skip
    const int m0  = blockIdx.y * 128;
    const int wm  = wid & 3;
    const int wn  = wid >> 2;

    if (bx < 2) {
        const float* av = (tid < 128) ? (bx ? asu : asl) : (bx ? adu : adl);
        avec[tid] = av[tid & 127];
    }

    // ---- B resident: 128 rows x 256 cols, hi+lo ----
    #pragma unroll
    for (int h = 0; h < 2; h++)
        #pragma unroll
        for (int t = 0; t < 16; t++) {
            int f = tid + t * 256;
            int n = f >> 5, seg = f & 31;       // 32 x 16B segments per row
            uint4 v = *(const uint4*)&g_Bt[h][bx][n][seg * 8];
            *(uint4*)(Bs + h * 128 * LDB + n * LDB + seg * 8) = v;
        }

    wmma::fragment<wmma::accumulator, 16, 16, 16, float> acc[2][4];
    #pragma unroll
    for (int i = 0; i < 2; i++)
        #pragma unroll
        for (int j = 0; j < 4; j++)
            wmma::fill_fragment(acc[i][j], 0.0f);

    // prefetch A chunk 0
    float4 xa[8];
    #pragma unroll
    for (int t = 0; t < 8; t++) {
        int f = tid + t * 256, row = f >> 4, k4 = f & 15;
        int m = m0 + row;
        xa[t] = (m < N_NODES) ? *(const float4*)(X + (size_t)m * IN_CH + k4 * 4)
                              : make_float4(0.f, 0.f, 0.f, 0.f);
    }

    for (int c = 0; c < NCHUNK; c++) {
        __nv_bfloat16* Ab = (__nv_bfloat16*)(smem + SM_A) + (c & 1) * 2 * ATILE;  // hi; lo at +ATILE
        #pragma unroll
        for (int t = 0; t < 8; t++) {
            int f = tid + t * 256, row = f >> 4, k4 = f & 15;
            float4 v = xa[t];
            __nv_bfloat162 h0 = __floats2bfloat162_rn(v.x, v.y);
            __nv_bfloat162 h1 = __floats2bfloat162_rn(v.z, v.w);
            __nv_bfloat162 l0 = __floats2bfloat162_rn(v.x - __bfloat162float(h0.x), v.y - __bfloat162float(h0.y));
            __nv_bfloat162 l1 = __floats2bfloat162_rn(v.z - __bfloat162float(h1.x), v.w - __bfloat162float(h1.y));
            int e = row * LDA + k4 * 4;
            *(uint2*)(Ab + e)         = make_uint2(*(uint32_t*)&h0, *(uint32_t*)&h1);
            *(uint2*)(Ab + ATILE + e) = make_uint2(*(uint32_t*)&l0, *(uint32_t*)&l1);
        }
        __syncthreads();    // also proves all warps done with HMMA on buffer (c-1)&1

        if (c + 1 < NCHUNK) {
            #pragma unroll
            for (int t = 0; t < 8; t++) {
                int f = tid + t * 256, row = f >> 4, k4 = f & 15;
                int m = m0 + row;
                xa[t] = (m < N_NODES) ? *(const float4*)(X + (size_t)m * IN_CH + (c + 1) * KC + k4 * 4)
                                      : make_float4(0.f, 0.f, 0.f, 0.f);
            }
        }

        #pragma unroll
        for (int ks = 0; ks < KC / 16; ks++) {
            wmma::fragment<wmma::matrix_a, 16, 16, 16, __nv_bfloat16, wmma::row_major> fa_hi[2], fa_lo[2];
            wmma::fragment<wmma::matrix_b, 16, 16, 16, __nv_bfloat16, wmma::col_major> fb_hi[4], fb_lo[4];
            #pragma unroll
            for (int i = 0; i < 2; i++) {
                const __nv_bfloat16* p = Ab + (wm * 32 + i * 16) * LDA + ks * 16;
                wmma::load_matrix_sync(fa_hi[i], p, LDA);
                wmma::load_matrix_sync(fa_lo[i], p + ATILE, LDA);
            }
            #pragma unroll
            for (int j = 0; j < 4; j++) {
                const __nv_bfloat16* p = Bs + (wn * 64 + j * 16) * LDB + c * KC + ks * 16;
                wmma::load_matrix_sync(fb_hi[j], p, LDB);
                wmma::load_matrix_sync(fb_lo[j], p + 128 * LDB, LDB);
            }
            #pragma unroll
            for (int i = 0; i < 2; i++)
                #pragma unroll
                for (int j = 0; j < 4; j++) {
                    wmma::mma_sync(acc[i][j], fa_hi[i], fb_hi[j], acc[i][j]);
                    wmma::mma_sync(acc[i][j], fa_lo[i], fb_hi[j], acc[i][j]);
                    wmma::mma_sync(acc[i][j], fa_hi[i], fb_lo[j], acc[i][j]);
                }
        }
    }
    __syncthreads();

    // --- epilogue: stage C in smem (reuse A region); fuse alpha / EPS / fp16 convert ---
    float* Cs = (float*)(smem + SM_A);          // 128*132*4 = 67584 <= 73728 OK
    #pragma unroll
    for (int i = 0; i < 2; i++)
        #pragma unroll
        for (int j = 0; j < 4; j++)
            wmma::store_matrix_sync(Cs + (wm * 32 + i * 16) * LDC + wn * 64 + j * 16,
                                    acc[i][j], LDC, wmma::mem_row_major);
    __syncthreads();

    {
        const int r = tid >> 1;                 // row in tile 0..127
        const int h = tid & 1;                  // half (= head) 0/1
        const int m = m0 + r;
        float ss = 0.f, dd = 0.f;
        if (m < N_NODES) {
            const float* crow = Cs + r * LDC + h * 64;
            if (bx == 2) {
                float* dst = g_xs + (size_t)m * HC + h * 64;
                #pragma unroll
                for (int q = 0; q < 16; q++) {
                    float4 v = *(const float4*)(crow + q * 4);
                    v.x *= EPS_F; v.y *= EPS_F; v.z *= EPS_F; v.w *= EPS_F;
                    *(float4*)(dst + q * 4) = v;
                }
            } else {
                __half* dst = g_xh[bx] + (size_t)m * HC + h * 64;
                const float* avs = avec + h * 64;
                const float* avd = avec + 128 + h * 64;
                #pragma unroll
                for (int q = 0; q < 16; q++) {
                    float4 v = *(const float4*)(crow + q * 4);
                    ss = fmaf(v.x, avs[q*4+0], ss); ss = fmaf(v.y, avs[q*4+1], ss);
                    ss = fmaf(v.z, avs[q*4+2], ss); ss = fmaf(v.w, avs[q*4+3], ss);
                    dd = fmaf(v.x, avd[q*4+0], dd); dd = fmaf(v.y, avd[q*4+1], dd);
                    dd = fmaf(v.z, avd[q*4+2], dd); dd = fmaf(v.w, avd[q*4+3], dd);
                    __half2 p0 = __floats2half2_rn(v.x, v.y);
                    __half2 p1 = __floats2half2_rn(v.z, v.w);
                    *(uint2*)(dst + q * 4) = make_uint2(*(uint32_t*)&p0, *(uint32_t*)&p1);
                }
            }
        }
        if (bx < 2) {
            float ss_o = __shfl_xor_sync(0xFFFFFFFF, ss, 1);
            float dd_o = __shfl_xor_sync(0xFFFFFFFF, dd, 1);
            if (h == 0 && m < N_NODES) {
                float s0 = (ss   > 0.f) ? ss   : 0.01f * ss;
                float s1 = (ss_o > 0.f) ? ss_o : 0.01f * ss_o;
                float d0 = (dd   > 0.f) ? dd   : 0.01f * dd;
                float d1 = (dd_o > 0.f) ? dd_o : 0.01f * dd_o;
                g_alpha[bx * 2 + 0][m] = make_float2(s0, s1);
                g_alpha[bx * 2 + 1][m] = make_float2(d0, d1);
            }
        }
    }
}

// ================= 4) per-edge head-softmax weight (2 heads -> sigmoid) =================
__global__ void edgew_kernel(const int* __restrict__ lsrc, const int* __restrict__ ltgt,
                             const int* __restrict__ usrc, const int* __restrict__ utgt) {
    int idx = blockIdx.x * blockDim.x + threadIdx.x;
    if (idx >= 2 * N_EDGES) return;
    int s = (idx >= N_EDGES) ? 1 : 0;
    int e = idx - s * N_EDGES;
    const int* src = s ? usrc : lsrc;
    const int* tgt = s ? utgt : ltgt;
    float2 as = g_alpha[s * 2][src[e]];
    float2 at = g_alpha[s * 2 + 1][tgt[e]];
    float d = (as.y + at.y) - (as.x + at.x);      // s1 - s0
    g_w[s][e] = 1.f / (1.f + __expf(d));
}

// ================= 5) fused aggregation: warp per target node, fp16 gathers =================
__global__ __launch_bounds__(256) void out_kernel(const int* __restrict__ lsrc,
                                                  const int* __restrict__ usrc,
                                                  float* __restrict__ out) {
    int warp = (blockIdx.x * blockDim.x + threadIdx.x) >> 5;
    int lane = threadIdx.x & 31;
    if (warp >= N_NODES) return;
    const int t = warp;
    const int head = lane >> 4;

    float4 acc = *(const float4*)(g_xs + (size_t)t * HC + lane * 4);   // skip (already *EPS)

    #pragma unroll
    for (int s = 0; s < 2; s++) {
        const int*   src = (s == 0) ? lsrc : usrc;
        const __half* xh = g_xh[s];
        const float* wv  = g_w[s];
        const int beg = g_rp[s][t], end = g_rp[s][t + 1];
        int e = beg;
        for (; e + 1 < end; e += 2) {
            int   sn0 = src[e],  sn1 = src[e + 1];
            float w00 = wv[e],   w01 = wv[e + 1];
            uint2 u0 = *(const uint2*)(xh + (size_t)sn0 * HC + lane * 4);
            uint2 u1 = *(const uint2*)(xh + (size_t)sn1 * HC + lane * 4);
            float wa = head ? (1.f - w00) : w00;
            float wb = head ? (1.f - w01) : w01;
            float2 a0 = __half22float2(*(__half2*)&u0.x);
            float2 a1 = __half22float2(*(__half2*)&u0.y);
            float2 b0 = __half22float2(*(__half2*)&u1.x);
            float2 b1 = __half22float2(*(__half2*)&u1.y);
            acc.x = fmaf(a0.x, wa, acc.x); acc.y = fmaf(a0.y, wa, acc.y);
            acc.z = fmaf(a1.x, wa, acc.z); acc.w = fmaf(a1.y, wa, acc.w);
            acc.x = fmaf(b0.x, wb, acc.x); acc.y = fmaf(b0.y, wb, acc.y);
            acc.z = fmaf(b1.x, wb, acc.z); acc.w = fmaf(b1.y, wb, acc.w);
        }
        if (e < end) {
            int   sn = src[e];
            float w0 = wv[e];
            float w  = head ? (1.f - w0) : w0;
            uint2 u = *(const uint2*)(xh + (size_t)sn * HC + lane * 4);
            float2 a0 = __half22float2(*(__half2*)&u.x);
            float2 a1 = __half22float2(*(__half2*)&u.y);
            acc.x = fmaf(a0.x, w, acc.x); acc.y = fmaf(a0.y, w, acc.y);
            acc.z = fmaf(a1.x, w, acc.z); acc.w = fmaf(a1.y, w, acc.w);
        }
    }
    acc.x = fmaxf(acc.x, 0.f);
    acc.y = fmaxf(acc.y, 0.f);
    acc.z = fmaxf(acc.z, 0.f);
    acc.w = fmaxf(acc.w, 0.f);
    *(float4*)(out + (size_t)t * HC + lane * 4) = acc;
}

// ================= launcher =================
extern "C" void kernel_launch(void* const* d_in, const int* in_sizes, int n_in,
                              void* d_out, int out_size) {
    const float* x    = (const float*)d_in[0];
    const int*   ltgt = (const int*)  d_in[1];
    const int*   lsrc = (const int*)  d_in[2];
    const int*   utgt = (const int*)  d_in[4];
    const int*   usrc = (const int*)  d_in[5];
    const float* Wl   = (const float*)d_in[7];
    const float* asl  = (const float*)d_in[8];
    const float* adl  = (const float*)d_in[9];
    const float* Wu   = (const float*)d_in[10];
    const float* asu  = (const float*)d_in[11];
    const float* adu  = (const float*)d_in[12];
    const float* Ws   = (const float*)d_in[13];
    float* out = (float*)d_out;

    cudaFuncSetAttribute(gemm_wmma, cudaFuncAttributeMaxDynamicSharedMemorySize, SM_TOTAL);

    prep_bt<<<(3 * HC * IN_CH + 255) / 256, 256>>>(Wl, Wu, Ws);
    rowptr_kernel<<<(N_NODES + 1 + 255) / 256, 256>>>(ltgt, utgt);

    dim3 ggrid(3, (N_NODES + 127) / 128);
    gemm_wmma<<<ggrid, 256, SM_TOTAL>>>(x, asl, adl, asu, adu);

    edgew_kernel<<<(2 * N_EDGES + 255) / 256, 256>>>(lsrc, ltgt, usrc, utgt);

    out_kernel<<<(N_NODES * 32 + 255) / 256, 256>>>(lsrc, usrc, out);
}

// round 9
// speedup vs baseline: 1.4294x; 1.4294x over previous
#include <cuda_runtime.h>
#include <cuda_fp16.h>
#include <mma.h>
#include <cstdint>

using namespace nvcuda;

#define N_NODES 50000
#define N_EDGES 800000
#define IN_CH   256
#define HC      128
#define EPS_F   1.000001f

// ================= scratch (static device arrays; no allocation) =================
__device__ __half g_Bt[3][HC][IN_CH];               // [mat][n][k]  (B = W^T, fp16)
__device__ __half g_xh[2][(size_t)N_NODES * HC];    // fp16 messages: x@Wl, x@Wu
__device__ float  g_xs[(size_t)N_NODES * HC];       // fp32 skip: (x@Ws)*EPS
__device__ float2 g_alpha[4][N_NODES];              // [l_src, l_dst, u_src, u_dst][n] = (h0,h1)
__device__ float  g_w[2][N_EDGES];                  // per-edge head-0 softmax weight
__device__ int    g_rp[2][N_NODES + 1];             // CSR row ptr (tgt sorted)

// ================= 1) B = W^T in fp16 =================
__global__ void prep_bt(const float* __restrict__ Wl, const float* __restrict__ Wu,
                        const float* __restrict__ Ws) {
    int i = blockIdx.x * blockDim.x + threadIdx.x;
    if (i >= 3 * HC * IN_CH) return;
    int mat = i / (HC * IN_CH);
    int r   = i % (HC * IN_CH);
    int n = r / IN_CH, k = r % IN_CH;
    const float* W = (mat == 0) ? Wl : (mat == 1 ? Wu : Ws);
    g_Bt[mat][n][k] = __float2half(W[k * HC + n]);
}

// ================= 2) row pointers via binary search =================
__global__ void rowptr_kernel(const int* __restrict__ ltgt, const int* __restrict__ utgt) {
    int t = blockIdx.x * blockDim.x + threadIdx.x;
    if (t > N_NODES) return;
    #pragma unroll
    for (int s = 0; s < 2; s++) {
        const int* tg = (s == 0) ? ltgt : utgt;
        int lo = 0, hi = N_EDGES;
        while (lo < hi) {
            int mid = (lo + hi) >> 1;
            if (tg[mid] < t) lo = mid + 1; else hi = mid;
        }
        g_rp[s][t] = lo;
    }
}

// ================= 3) single-pass fp16 wmma GEMM, fused alpha + EPS epilogue =================
// grid = (3 matrices, 391 M-tiles), 256 threads (8 warps, 4x2 warp grid, warp tile 32x64)
#define KC      64
#define NCHUNK  (IN_CH / KC)     // 4
#define LDA     72               // 64 + 8 pad (fp16); odd x8 granules -> LDSM conflict-free
#define LDB     264              // 256 + 8 pad (fp16)
#define ATILE   (128 * LDA)      // elements per A buffer
#define SM_AVEC 0                // 256 floats
#define SM_A    1024             // 2 buffers x 18432 B
#define SM_B    (SM_A + 2 * ATILE * 2)          // 1024 + 36864 = 37888
#define SM_TOTAL (SM_B + 128 * LDB * 2)         // 37888 + 67584 = 105472 B -> 2 CTAs/SM
#define LDC     132              // fp32 C staging stride

__global__ __launch_bounds__(256) void gemm_wmma(const float* __restrict__ X,
                                                 const float* __restrict__ asl, const float* __restrict__ adl,
                                                 const float* __restrict__ asu, const float* __restrict__ adu) {
    extern __shared__ __align__(16) char smem[];
    float* avec = (float*)(smem + SM_AVEC);
    __half* Bs = (__half*)(smem + SM_B);

    const int tid = threadIdx.x;
    const int wid = tid >> 5;
    const int bx  = blockIdx.x;                 // matrix 0=lower,1=upper,2=skip
    const int m0  = blockIdx.y * 128;
    const int wm  = wid & 3;
    const int wn  = wid >> 2;

    if (bx < 2) {
        const float* av = (tid < 128) ? (bx ? asu : asl) : (bx ? adu : adl);
        avec[tid] = av[tid & 127];
    }

    // ---- B resident: 128 rows x 256 cols fp16 ----
    #pragma unroll
    for (int t = 0; t < 16; t++) {
        int f = tid + t * 256;
        int n = f >> 5, seg = f & 31;           // 32 x 16B segments per row
        uint4 v = *(const uint4*)&g_Bt[bx][n][seg * 8];
        *(uint4*)(Bs + n * LDB + seg * 8) = v;
    }

    wmma::fragment<wmma::accumulator, 16, 16, 16, float> acc[2][4];
    #pragma unroll
    for (int i = 0; i < 2; i++)
        #pragma unroll
        for (int j = 0; j < 4; j++)
            wmma::fill_fragment(acc[i][j], 0.0f);

    // prefetch A chunk 0
    float4 xa[8];
    #pragma unroll
    for (int t = 0; t < 8; t++) {
        int f = tid + t * 256, row = f >> 4, k4 = f & 15;
        int m = m0 + row;
        xa[t] = (m < N_NODES) ? *(const float4*)(X + (size_t)m * IN_CH + k4 * 4)
                              : make_float4(0.f, 0.f, 0.f, 0.f);
    }

    for (int c = 0; c < NCHUNK; c++) {
        __half* Ab = (__half*)(smem + SM_A) + (c & 1) * ATILE;
        #pragma unroll
        for (int t = 0; t < 8; t++) {
            int f = tid + t * 256, row = f >> 4, k4 = f & 15;
            float4 v = xa[t];
            __half2 h0 = __floats2half2_rn(v.x, v.y);
            __half2 h1 = __floats2half2_rn(v.z, v.w);
            *(uint2*)(Ab + row * LDA + k4 * 4) = make_uint2(*(uint32_t*)&h0, *(uint32_t*)&h1);
        }
        __syncthreads();    // proves all warps done with HMMA on buffer (c-1)&1

        if (c + 1 < NCHUNK) {
            #pragma unroll
            for (int t = 0; t < 8; t++) {
                int f = tid + t * 256, row = f >> 4, k4 = f & 15;
                int m = m0 + row;
                xa[t] = (m < N_NODES) ? *(const float4*)(X + (size_t)m * IN_CH + (c + 1) * KC + k4 * 4)
                                      : make_float4(0.f, 0.f, 0.f, 0.f);
            }
        }

        #pragma unroll
        for (int ks = 0; ks < KC / 16; ks++) {
            wmma::fragment<wmma::matrix_a, 16, 16, 16, __half, wmma::row_major> fa[2];
            wmma::fragment<wmma::matrix_b, 16, 16, 16, __half, wmma::col_major> fb[4];
            #pragma unroll
            for (int i = 0; i < 2; i++)
                wmma::load_matrix_sync(fa[i], Ab + (wm * 32 + i * 16) * LDA + ks * 16, LDA);
            #pragma unroll
            for (int j = 0; j < 4; j++)
                wmma::load_matrix_sync(fb[j], Bs + (wn * 64 + j * 16) * LDB + c * KC + ks * 16, LDB);
            #pragma unroll
            for (int i = 0; i < 2; i++)
                #pragma unroll
                for (int j = 0; j < 4; j++)
                    wmma::mma_sync(acc[i][j], fa[i], fb[j], acc[i][j]);
        }
    }
    __syncthreads();

    // --- epilogue: stage C in smem (A+B regions are dead now); fuse alpha / EPS / fp16 ---
    float* Cs = (float*)(smem + SM_A);          // 128*132*4 = 67584 B, fits
    #pragma unroll
    for (int i = 0; i < 2; i++)
        #pragma unroll
        for (int j = 0; j < 4; j++)
            wmma::store_matrix_sync(Cs + (wm * 32 + i * 16) * LDC + wn * 64 + j * 16,
                                    acc[i][j], LDC, wmma::mem_row_major);
    __syncthreads();

    {
        const int r = tid >> 1;                 // row in tile 0..127
        const int h = tid & 1;                  // half (= head) 0/1
        const int m = m0 + r;
        float ss = 0.f, dd = 0.f;
        if (m < N_NODES) {
            const float* crow = Cs + r * LDC + h * 64;
            if (bx == 2) {
                float* dst = g_xs + (size_t)m * HC + h * 64;
                #pragma unroll
                for (int q = 0; q < 16; q++) {
                    float4 v = *(const float4*)(crow + q * 4);
                    v.x *= EPS_F; v.y *= EPS_F; v.z *= EPS_F; v.w *= EPS_F;
                    *(float4*)(dst + q * 4) = v;
                }
            } else {
                __half* dst = g_xh[bx] + (size_t)m * HC + h * 64;
                const float* avs = avec + h * 64;
                const float* avd = avec + 128 + h * 64;
                #pragma unroll
                for (int q = 0; q < 16; q++) {
                    float4 v = *(const float4*)(crow + q * 4);
                    ss = fmaf(v.x, avs[q*4+0], ss); ss = fmaf(v.y, avs[q*4+1], ss);
                    ss = fmaf(v.z, avs[q*4+2], ss); ss = fmaf(v.w, avs[q*4+3], ss);
                    dd = fmaf(v.x, avd[q*4+0], dd); dd = fmaf(v.y, avd[q*4+1], dd);
                    dd = fmaf(v.z, avd[q*4+2], dd); dd = fmaf(v.w, avd[q*4+3], dd);
                    __half2 p0 = __floats2half2_rn(v.x, v.y);
                    __half2 p1 = __floats2half2_rn(v.z, v.w);
                    *(uint2*)(dst + q * 4) = make_uint2(*(uint32_t*)&p0, *(uint32_t*)&p1);
                }
            }
        }
        if (bx < 2) {
            float ss_o = __shfl_xor_sync(0xFFFFFFFF, ss, 1);
            float dd_o = __shfl_xor_sync(0xFFFFFFFF, dd, 1);
            if (h == 0 && m < N_NODES) {
                float s0 = (ss   > 0.f) ? ss   : 0.01f * ss;
                float s1 = (ss_o > 0.f) ? ss_o : 0.01f * ss_o;
                float d0 = (dd   > 0.f) ? dd   : 0.01f * dd;
                float d1 = (dd_o > 0.f) ? dd_o : 0.01f * dd_o;
                g_alpha[bx * 2 + 0][m] = make_float2(s0, s1);
                g_alpha[bx * 2 + 1][m] = make_float2(d0, d1);
            }
        }
    }
}

// ================= 4) per-edge head-softmax weight (2 heads -> sigmoid) =================
__global__ void edgew_kernel(const int* __restrict__ lsrc, const int* __restrict__ ltgt,
                             const int* __restrict__ usrc, const int* __restrict__ utgt) {
    int idx = blockIdx.x * blockDim.x + threadIdx.x;
    if (idx >= 2 * N_EDGES) return;
    int s = (idx >= N_EDGES) ? 1 : 0;
    int e = idx - s * N_EDGES;
    const int* src = s ? usrc : lsrc;
    const int* tgt = s ? utgt : ltgt;
    float2 as = g_alpha[s * 2][src[e]];
    float2 at = g_alpha[s * 2 + 1][tgt[e]];
    float d = (as.y + at.y) - (as.x + at.x);      // s1 - s0
    g_w[s][e] = 1.f / (1.f + __expf(d));
}

// ================= 5) fused aggregation: warp per target node, fp16 gathers =================
__global__ __launch_bounds__(256) void out_kernel(const int* __restrict__ lsrc,
                                                  const int* __restrict__ usrc,
                                                  float* __restrict__ out) {
    int warp = (blockIdx.x * blockDim.x + threadIdx.x) >> 5;
    int lane = threadIdx.x & 31;
    if (warp >= N_NODES) return;
    const int t = warp;
    const int head = lane >> 4;

    float4 acc = *(const float4*)(g_xs + (size_t)t * HC + lane * 4);   // skip (already *EPS)

    #pragma unroll
    for (int s = 0; s < 2; s++) {
        const int*   src = (s == 0) ? lsrc : usrc;
        const __half* xh = g_xh[s];
        const float* wv  = g_w[s];
        const int beg = g_rp[s][t], end = g_rp[s][t + 1];
        int e = beg;
        for (; e + 1 < end; e += 2) {
            int   sn0 = src[e],  sn1 = src[e + 1];
            float w00 = wv[e],   w01 = wv[e + 1];
            uint2 u0 = *(const uint2*)(xh + (size_t)sn0 * HC + lane * 4);
            uint2 u1 = *(const uint2*)(xh + (size_t)sn1 * HC + lane * 4);
            float wa = head ? (1.f - w00) : w00;
            float wb = head ? (1.f - w01) : w01;
            float2 a0 = __half22float2(*(__half2*)&u0.x);
            float2 a1 = __half22float2(*(__half2*)&u0.y);
            float2 b0 = __half22float2(*(__half2*)&u1.x);
            float2 b1 = __half22float2(*(__half2*)&u1.y);
            acc.x = fmaf(a0.x, wa, acc.x); acc.y = fmaf(a0.y, wa, acc.y);
            acc.z = fmaf(a1.x, wa, acc.z); acc.w = fmaf(a1.y, wa, acc.w);
            acc.x = fmaf(b0.x, wb, acc.x); acc.y = fmaf(b0.y, wb, acc.y);
            acc.z = fmaf(b1.x, wb, acc.z); acc.w = fmaf(b1.y, wb, acc.w);
        }
        if (e < end) {
            int   sn = src[e];
            float w0 = wv[e];
            float w  = head ? (1.f - w0) : w0;
            uint2 u = *(const uint2*)(xh + (size_t)sn * HC + lane * 4);
            float2 a0 = __half22float2(*(__half2*)&u.x);
            float2 a1 = __half22float2(*(__half2*)&u.y);
            acc.x = fmaf(a0.x, w, acc.x); acc.y = fmaf(a0.y, w, acc.y);
            acc.z = fmaf(a1.x, w, acc.z); acc.w = fmaf(a1.y, w, acc.w);
        }
    }
    acc.x = fmaxf(acc.x, 0.f);
    acc.y = fmaxf(acc.y, 0.f);
    acc.z = fmaxf(acc.z, 0.f);
    acc.w = fmaxf(acc.w, 0.f);
    *(float4*)(out + (size_t)t * HC + lane * 4) = acc;
}

// ================= launcher =================
extern "C" void kernel_launch(void* const* d_in, const int* in_sizes, int n_in,
                              void* d_out, int out_size) {
    const float* x    = (const float*)d_in[0];
    const int*   ltgt = (const int*)  d_in[1];
    const int*   lsrc = (const int*)  d_in[2];
    const int*   utgt = (const int*)  d_in[4];
    const int*   usrc = (const int*)  d_in[5];
    const float* Wl   = (const float*)d_in[7];
    const float* asl  = (const float*)d_in[8];
    const float* adl  = (const float*)d_in[9];
    const float* Wu   = (const float*)d_in[10];
    const float* asu  = (const float*)d_in[11];
    const float* adu  = (const float*)d_in[12];
    const float* Ws   = (const float*)d_in[13];
    float* out = (float*)d_out;

    cudaFuncSetAttribute(gemm_wmma, cudaFuncAttributeMaxDynamicSharedMemorySize, SM_TOTAL);

    prep_bt<<<(3 * HC * IN_CH + 255) / 256, 256>>>(Wl, Wu, Ws);
    rowptr_kernel<<<(N_NODES + 1 + 255) / 256, 256>>>(ltgt, utgt);

    dim3 ggrid(3, (N_NODES + 127) / 128);
    gemm_wmma<<<ggrid, 256, SM_TOTAL>>>(x, asl, adl, asu, adu);

    edgew_kernel<<<(2 * N_EDGES + 255) / 256, 256>>>(lsrc, ltgt, usrc, utgt);

    out_kernel<<<(N_NODES * 32 + 255) / 256, 256>>>(lsrc, usrc, out);
}

// round 11
// speedup vs baseline: 1.4458x; 1.0115x over previous
#include <cuda_runtime.h>
#include <cuda_fp16.h>
#include <mma.h>
#include <cstdint>

using namespace nvcuda;

#define N_NODES 50000
#define N_EDGES 800000
#define IN_CH   256
#define HC      128
#define EPS_F   1.000001f

// ================= scratch (static device arrays; no allocation) =================
__device__ __half g_X16[(size_t)N_NODES * IN_CH];   // X in fp16
__device__ __half g_Bt[3][HC][IN_CH];               // [mat][n][k]  (B = W^T, fp16; skip pre-scaled by EPS)
__device__ __half g_xh[2][(size_t)N_NODES * HC];    // fp16 messages: x@Wl, x@Wu
__device__ float  g_xs[(size_t)N_NODES * HC];       // fp32 skip: (x@Ws)*EPS
__device__ float2 g_alpha[4][N_NODES];              // [l_src, l_dst, u_src, u_dst][n] = (h0,h1)
__device__ float  g_w[2][N_EDGES];                  // per-edge head-0 softmax weight
__device__ int    g_rp[2][N_NODES + 1];             // CSR row ptr (tgt sorted)

__device__ __forceinline__ uint32_t smem_u32(const void* p) {
    uint32_t a;
    asm("{ .reg .u64 t; cvta.to.shared.u64 t, %1; cvt.u32.u64 %0, t; }" : "=r"(a) : "l"(p));
    return a;
}
__device__ __forceinline__ void cp16(uint32_t dst, const void* src, int nbytes) {
    asm volatile("cp.async.cg.shared.global [%0], [%1], 16, %2;" :: "r"(dst), "l"(src), "r"(nbytes));
}
#define CP_COMMIT() asm volatile("cp.async.commit_group;" ::: "memory")
#define CP_WAIT0()  asm volatile("cp.async.wait_group 0;" ::: "memory")

// ================= 0) X -> fp16 =================
__global__ void x2h_kernel(const float* __restrict__ X) {
    int f = blockIdx.x * blockDim.x + threadIdx.x;       // one per 8 elements
    if (f >= N_NODES * IN_CH / 8) return;
    size_t base = (size_t)f * 8;
    float4 v0 = *(const float4*)(X + base);
    float4 v1 = *(const float4*)(X + base + 4);
    __half2 h0 = __floats2half2_rn(v0.x, v0.y);
    __half2 h1 = __floats2half2_rn(v0.z, v0.w);
    __half2 h2 = __floats2half2_rn(v1.x, v1.y);
    __half2 h3 = __floats2half2_rn(v1.z, v1.w);
    uint4 o = make_uint4(*(uint32_t*)&h0, *(uint32_t*)&h1, *(uint32_t*)&h2, *(uint32_t*)&h3);
    *(uint4*)(g_X16 + base) = o;
}

// ================= 1) B = W^T in fp16 (skip matrix pre-scaled by EPS) =================
__global__ void prep_bt(const float* __restrict__ Wl, const float* __restrict__ Wu,
                        const float* __restrict__ Ws) {
    int i = blockIdx.x * blockDim.x + threadIdx.x;
    if (i >= 3 * HC * IN_CH) return;
    int mat = i / (HC * IN_CH);
    int r   = i % (HC * IN_CH);
    int n = r / IN_CH, k = r % IN_CH;
    const float* W = (mat == 0) ? Wl : (mat == 1 ? Wu : Ws);
    float w = W[k * HC + n];
    if (mat == 2) w *= EPS_F;
    g_Bt[mat][n][k] = __float2half(w);
}

// ================= 2) row pointers via binary search =================
__global__ void rowptr_kernel(const int* __restrict__ ltgt, const int* __restrict__ utgt) {
    int t = blockIdx.x * blockDim.x + threadIdx.x;
    if (t > N_NODES) return;
    #pragma unroll
    for (int s = 0; s < 2; s++) {
        const int* tg = (s == 0) ? ltgt : utgt;
        int lo = 0, hi = N_EDGES;
        while (lo < hi) {
            int mid = (lo + hi) >> 1;
            if (tg[mid] < t) lo = mid + 1; else hi = mid;
        }
        g_rp[s][t] = lo;
    }
}

// ================= 3) fp16 wmma GEMM: BM=256, cp.async A, B resident =================
// grid = (3 matrices, 196 M-tiles), 256 threads (8 warps, 4x2 warp grid, warp tile 64x64)
#define BM      256
#define KC      64
#define NCHUNK  (IN_CH / KC)     // 4
#define LDA     72               // 64 + 8 pad (fp16); 144B rows, 16B aligned, odd granules
#define LDB     264
#define ABUF    (BM * LDA)       // halves per A buffer (36864 B)
#define SM_AVEC 0                // 256 floats
#define SM_A    1024
#define SM_B    (SM_A + 2 * ABUF * 2)           // 1024 + 73728 = 74752
#define SM_TOTAL (SM_B + 128 * LDB * 2)         // 74752 + 67584 = 142336 B
#define LDC     132

__global__ __launch_bounds__(256) void gemm_wmma(const float* __restrict__ asl, const float* __restrict__ adl,
                                                 const float* __restrict__ asu, const float* __restrict__ adu) {
    extern __shared__ __align__(16) char smem[];
    float* avec = (float*)(smem + SM_AVEC);
    __half* Bs = (__half*)(smem + SM_B);
    const uint32_t smA = smem_u32(smem) + SM_A;

    const int tid = threadIdx.x;
    const int wid = tid >> 5;
    const int bx  = blockIdx.x;                 // matrix 0=lower,1=upper,2=skip
    const int m0  = blockIdx.y * BM;
    const int wm  = wid & 3;                    // 4 row groups of 64
    const int wn  = wid >> 2;                   // 2 col groups of 64

    if (bx < 2) {
        const float* av = (tid < 128) ? (bx ? asu : asl) : (bx ? adu : adl);
        avec[tid] = av[tid & 127];
    }

    // ---- B resident: 128 rows x 256 cols fp16 ----
    #pragma unroll
    for (int t = 0; t < 16; t++) {
        int f = tid + t * 256;
        int n = f >> 5, seg = f & 31;
        uint4 v = *(const uint4*)&g_Bt[bx][n][seg * 8];
        *(uint4*)(Bs + n * LDB + seg * 8) = v;
    }

    wmma::fragment<wmma::accumulator, 16, 16, 16, float> acc[4][4];
    #pragma unroll
    for (int i = 0; i < 4; i++)
        #pragma unroll
        for (int j = 0; j < 4; j++)
            wmma::fill_fragment(acc[i][j], 0.0f);

    // ---- cp.async A chunk issue: 256 rows x 64 halves (128B = 8 segs/row) ----
    auto issue_chunk = [&](int c) {
        uint32_t Ab = smA + (c & 1) * (ABUF * 2);
        #pragma unroll
        for (int t = 0; t < 8; t++) {
            int f = tid + t * 256;               // 0..2047
            int row = f >> 3, seg = f & 7;
            int m = m0 + row;
            int mc = (m < N_NODES) ? m : (N_NODES - 1);
            const __half* src = g_X16 + (size_t)mc * IN_CH + c * KC + seg * 8;
            cp16(Ab + (row * LDA + seg * 8) * 2, src, (m < N_NODES) ? 16 : 0);
        }
        CP_COMMIT();
    };

    issue_chunk(0);

    for (int c = 0; c < NCHUNK; c++) {
        CP_WAIT0();          // chunk c landed (this thread's groups)
        __syncthreads();     // all threads' copies visible; all warps done mma c-1
        if (c + 1 < NCHUNK) issue_chunk(c + 1);   // overlaps with mma on chunk c

        const __half* Ab = (const __half*)(smem + SM_A) + (c & 1) * ABUF;
        #pragma unroll
        for (int ks = 0; ks < KC / 16; ks++) {
            wmma::fragment<wmma::matrix_a, 16, 16, 16, __half, wmma::row_major> fa[4];
            wmma::fragment<wmma::matrix_b, 16, 16, 16, __half, wmma::col_major> fb[4];
            #pragma unroll
            for (int i = 0; i < 4; i++)
                wmma::load_matrix_sync(fa[i], Ab + (wm * 64 + i * 16) * LDA + ks * 16, LDA);
            #pragma unroll
            for (int j = 0; j < 4; j++)
                wmma::load_matrix_sync(fb[j], Bs + (wn * 64 + j * 16) * LDB + c * KC + ks * 16, LDB);
            #pragma unroll
            for (int i = 0; i < 4; i++)
                #pragma unroll
                for (int j = 0; j < 4; j++)
                    wmma::mma_sync(acc[i][j], fa[i], fb[j], acc[i][j]);
        }
    }
    __syncthreads();

    // --- epilogue: stage C (256 x 132 fp32 = 135168 B, fits in A+B region) ---
    float* Cs = (float*)(smem + SM_A);
    #pragma unroll
    for (int i = 0; i < 4; i++)
        #pragma unroll
        for (int j = 0; j < 4; j++)
            wmma::store_matrix_sync(Cs + (wm * 64 + i * 16) * LDC + wn * 64 + j * 16,
                                    acc[i][j], LDC, wmma::mem_row_major);
    __syncthreads();

    {
        const int r = tid;                      // one thread per row
        const int m = m0 + r;
        if (m < N_NODES) {
            const float* crow = Cs + r * LDC;
            if (bx == 2) {
                float* dst = g_xs + (size_t)m * HC;
                #pragma unroll
                for (int q = 0; q < 32; q++)
                    *(float4*)(dst + q * 4) = *(const float4*)(crow + q * 4);
            } else {
                __half* dst = g_xh[bx] + (size_t)m * HC;
                float s0 = 0.f, s1 = 0.f, d0 = 0.f, d1 = 0.f;
                #pragma unroll
                for (int q = 0; q < 32; q++) {
                    float4 v = *(const float4*)(crow + q * 4);
                    const int cbase = q * 4;
                    const bool h1f = (cbase >= 64);
                    float* sacc = h1f ? &s1 : &s0;
                    float* dacc = h1f ? &d1 : &d0;
                    *sacc = fmaf(v.x, avec[cbase+0], *sacc); *sacc = fmaf(v.y, avec[cbase+1], *sacc);
                    *sacc = fmaf(v.z, avec[cbase+2], *sacc); *sacc = fmaf(v.w, avec[cbase+3], *sacc);
                    *dacc = fmaf(v.x, avec[128+cbase+0], *dacc); *dacc = fmaf(v.y, avec[128+cbase+1], *dacc);
                    *dacc = fmaf(v.z, avec[128+cbase+2], *dacc); *dacc = fmaf(v.w, avec[128+cbase+3], *dacc);
                    __half2 p0 = __floats2half2_rn(v.x, v.y);
                    __half2 p1 = __floats2half2_rn(v.z, v.w);
                    *(uint2*)(dst + cbase) = make_uint2(*(uint32_t*)&p0, *(uint32_t*)&p1);
                }
                s0 = (s0 > 0.f) ? s0 : 0.01f * s0;
                s1 = (s1 > 0.f) ? s1 : 0.01f * s1;
                d0 = (d0 > 0.f) ? d0 : 0.01f * d0;
                d1 = (d1 > 0.f) ? d1 : 0.01f * d1;
                g_alpha[bx * 2 + 0][m] = make_float2(s0, s1);
                g_alpha[bx * 2 + 1][m] = make_float2(d0, d1);
            }
        }
    }
}

// ================= 4) per-edge head-softmax weight (2 heads -> sigmoid) =================
__global__ void edgew_kernel(const int* __restrict__ lsrc, const int* __restrict__ ltgt,
                             const int* __restrict__ usrc, const int* __restrict__ utgt) {
    int idx = blockIdx.x * blockDim.x + threadIdx.x;
    if (idx >= 2 * N_EDGES) return;
    int s = (idx >= N_EDGES) ? 1 : 0;
    int e = idx - s * N_EDGES;
    const int* src = s ? usrc : lsrc;
    const int* tgt = s ? utgt : ltgt;
    float2 as = g_alpha[s * 2][src[e]];
    float2 at = g_alpha[s * 2 + 1][tgt[e]];
    float d = (as.y + at.y) - (as.x + at.x);      // s1 - s0
    g_w[s][e] = 1.f / (1.f + __expf(d));
}

// ================= 5) fused aggregation: warp per target node, fp16 gathers =================
__global__ __launch_bounds__(256) void out_kernel(const int* __restrict__ lsrc,
                                                  const int* __restrict__ usrc,
                                                  float* __restrict__ out) {
    int warp = (blockIdx.x * blockDim.x + threadIdx.x) >> 5;
    int lane = threadIdx.x & 31;
    if (warp >= N_NODES) return;
    const int t = warp;
    const int head = lane >> 4;

    float4 acc = *(const float4*)(g_xs + (size_t)t * HC + lane * 4);   // skip (already *EPS)

    #pragma unroll
    for (int s = 0; s < 2; s++) {
        const int*   src = (s == 0) ? lsrc : usrc;
        const __half* xh = g_xh[s];
        const float* wv  = g_w[s];
        const int beg = g_rp[s][t], end = g_rp[s][t + 1];
        int e = beg;
        for (; e + 1 < end; e += 2) {
            int   sn0 = src[e],  sn1 = src[e + 1];
            float w00 = wv[e],   w01 = wv[e + 1];
            uint2 u0 = *(const uint2*)(xh + (size_t)sn0 * HC + lane * 4);
            uint2 u1 = *(const uint2*)(xh + (size_t)sn1 * HC + lane * 4);
            float wa = head ? (1.f - w00) : w00;
            float wb = head ? (1.f - w01) : w01;
            float2 a0 = __half22float2(*(__half2*)&u0.x);
            float2 a1 = __half22float2(*(__half2*)&u0.y);
            float2 b0 = __half22float2(*(__half2*)&u1.x);
            float2 b1 = __half22float2(*(__half2*)&u1.y);
            acc.x = fmaf(a0.x, wa, acc.x); acc.y = fmaf(a0.y, wa, acc.y);
            acc.z = fmaf(a1.x, wa, acc.z); acc.w = fmaf(a1.y, wa, acc.w);
            acc.x = fmaf(b0.x, wb, acc.x); acc.y = fmaf(b0.y, wb, acc.y);
            acc.z = fmaf(b1.x, wb, acc.z); acc.w = fmaf(b1.y, wb, acc.w);
        }
        if (e < end) {
            int   sn = src[e];
            float w0 = wv[e];
            float w  = head ? (1.f - w0) : w0;
            uint2 u = *(const uint2*)(xh + (size_t)sn * HC + lane * 4);
            float2 a0 = __half22float2(*(__half2*)&u.x);
            float2 a1 = __half22float2(*(__half2*)&u.y);
            acc.x = fmaf(a0.x, w, acc.x); acc.y = fmaf(a0.y, w, acc.y);
            acc.z = fmaf(a1.x, w, acc.z); acc.w = fmaf(a1.y, w, acc.w);
        }
    }
    acc.x = fmaxf(acc.x, 0.f);
    acc.y = fmaxf(acc.y, 0.f);
    acc.z = fmaxf(acc.z, 0.f);
    acc.w = fmaxf(acc.w, 0.f);
    *(float4*)(out + (size_t)t * HC + lane * 4) = acc;
}

// ================= launcher =================
extern "C" void kernel_launch(void* const* d_in, const int* in_sizes, int n_in,
                              void* d_out, int out_size) {
    const float* x    = (const float*)d_in[0];
    const int*   ltgt = (const int*)  d_in[1];
    const int*   lsrc = (const int*)  d_in[2];
    const int*   utgt = (const int*)  d_in[4];
    const int*   usrc = (const int*)  d_in[5];
    const float* Wl   = (const float*)d_in[7];
    const float* asl  = (const float*)d_in[8];
    const float* adl  = (const float*)d_in[9];
    const float* Wu   = (const float*)d_in[10];
    const float* asu  = (const float*)d_in[11];
    const float* adu  = (const float*)d_in[12];
    const float* Ws   = (const float*)d_in[13];
    float* out = (float*)d_out;

    cudaFuncSetAttribute(gemm_wmma, cudaFuncAttributeMaxDynamicSharedMemorySize, SM_TOTAL);

    x2h_kernel<<<(N_NODES * IN_CH / 8 + 255) / 256, 256>>>(x);
    prep_bt<<<(3 * HC * IN_CH + 255) / 256, 256>>>(Wl, Wu, Ws);
    rowptr_kernel<<<(N_NODES + 1 + 255) / 256, 256>>>(ltgt, utgt);

    dim3 ggrid(3, (N_NODES + BM - 1) / BM);
    gemm_wmma<<<ggrid, 256, SM_TOTAL>>>(asl, adl, asu, adu);

    edgew_kernel<<<(2 * N_EDGES + 255) / 256, 256>>>(lsrc, ltgt, usrc, utgt);

    out_kernel<<<(N_NODES * 32 + 255) / 256, 256>>>(lsrc, usrc, out);
}